// round 6
// baseline (speedup 1.0000x reference)
#include <cuda_runtime.h>
#include <cstdint>

// ---------------- problem constants ----------------
#define T_SIZE 32768
#define TMASK  32767u
#define P1 2654435761u
#define P2 805459861u
#define MAXN (1 << 20)
#define NBINS 32768
#define BLK2 128

// scratch (no cudaMalloc allowed)
__device__ float4 g_tmp[MAXN];    // compacted, unsorted
__device__ float4 g_pts[MAXN];    // morton-sorted
__device__ unsigned g_keys[MAXN];
__device__ int g_hist[NBINS];
__device__ int g_off[NBINS];
__device__ int g_blocksum[64];
__device__ int g_count;

__device__ __forceinline__ unsigned part5(unsigned x) {
    return ((x & 16u) << 8) | ((x & 8u) << 6) | ((x & 4u) << 4) |
           ((x & 2u) << 2) | (x & 1u);
}

// ---------------- kernel 1: mask + defaults + compact + histogram ------
__global__ void k_mask_compact(const float* __restrict__ xyz,
                               const float* __restrict__ bmin,
                               const float* __restrict__ bmax,
                               float* __restrict__ out, int N)
{
    int i = blockIdx.x * blockDim.x + threadIdx.x;
    bool inb = false;
    float cx = 0.f, cy = 0.f, cz = 0.f;

    if (i < N) {
        float bx0 = bmin[0], by0 = bmin[1], bz0 = bmin[2];
        float bx1 = bmax[0], by1 = bmax[1], bz1 = bmax[2];
        float x = xyz[3 * i + 0];
        float y = xyz[3 * i + 1];
        float z = xyz[3 * i + 2];
        cx = (x - bx0) / (bx1 - bx0);
        cy = (y - by0) / (by1 - by0);
        cz = (z - bz0) / (bz1 - bz0);
        inb = (cx >= 0.f) & (cx <= 1.f) &
              (cy >= 0.f) & (cy <= 1.f) &
              (cz >= 0.f) & (cz <= 1.f);

        out[i] = inb ? 1.f : 0.f;
        float* dxyz = out + N;
        float* drot = out + (size_t)4 * N;
        dxyz[3 * i + 0] = 0.f;
        dxyz[3 * i + 1] = 0.f;
        dxyz[3 * i + 2] = 0.f;
        drot[4 * i + 0] = 1.f;
        drot[4 * i + 1] = 0.f;
        drot[4 * i + 2] = 0.f;
        drot[4 * i + 3] = 0.f;
    }

    unsigned m = __ballot_sync(0xffffffffu, inb);
    if (inb) {
        int lane = threadIdx.x & 31;
        int leader = __ffs(m) - 1;
        int base = 0;
        if (lane == leader) base = atomicAdd(&g_count, __popc(m));
        base = __shfl_sync(m, base, leader);
        int slot = base + __popc(m & ((1u << lane) - 1u));
        cx = fminf(fmaxf(cx, 0.f), 1.f);
        cy = fminf(fmaxf(cy, 0.f), 1.f);
        cz = fminf(fmaxf(cz, 0.f), 1.f);
        g_tmp[slot] = make_float4(cx, cy, cz, __int_as_float(i));
        unsigned qx = min(31u, (unsigned)(cx * 32.f));
        unsigned qy = min(31u, (unsigned)(cy * 32.f));
        unsigned qz = min(31u, (unsigned)(cz * 32.f));
        unsigned key = part5(qx) | (part5(qy) << 1) | (part5(qz) << 2);
        g_keys[slot] = key;
        atomicAdd(&g_hist[key], 1);
    }
}

// ---------------- scan phase A: 64 blocks, local scan of 512 bins -------
__global__ void k_scanA()
{
    __shared__ int wsum[16];
    int b = blockIdx.x;               // 64 blocks x 512 bins
    int tid = threadIdx.x;            // 128 threads, 4 bins each
    int base = b * 512 + tid * 4;
    int4 c = *(const int4*)&g_hist[base];
    int s = c.x + c.y + c.z + c.w;

    int lane = tid & 31, wid = tid >> 5;
    int v = s;
    #pragma unroll
    for (int d = 1; d < 32; d <<= 1) {
        int t = __shfl_up_sync(0xffffffffu, v, d);
        if (lane >= d) v += t;
    }
    if (lane == 31) wsum[wid] = v;
    __syncthreads();
    if (tid == 0) {
        int acc = 0;
        #pragma unroll
        for (int w = 0; w < 4; w++) { int t = wsum[w]; wsum[w] = acc; acc += t; }
        g_blocksum[b] = acc;
    }
    __syncthreads();
    int excl = v - s + wsum[wid];
    int4 o;
    o.x = excl; o.y = excl + c.x; o.z = o.y + c.y; o.w = o.z + c.z;
    *(int4*)&g_off[base] = o;
}

// ---------------- scan phase B: add block prefixes (1 block) ------------
__global__ void k_scanB()
{
    __shared__ int pre[64];
    int tid = threadIdx.x;            // 512 threads
    if (tid == 0) {
        int acc = 0;
        #pragma unroll
        for (int b = 0; b < 64; b++) { int t = g_blocksum[b]; pre[b] = acc; acc += t; }
    }
    __syncthreads();
    // 64 blocks' worth of bins, add prefix
    for (int idx = tid; idx < NBINS / 4; idx += 512) {
        int b = idx / 128;            // 128 int4 per block-segment
        int add = pre[b];
        int4 v = *(int4*)&g_off[idx * 4];
        v.x += add; v.y += add; v.z += add; v.w += add;
        *(int4*)&g_off[idx * 4] = v;
    }
}

// ---------------- scatter into sorted order -----------------------------
__global__ void k_scatter()
{
    int cnt = g_count;
    for (int i = blockIdx.x * blockDim.x + threadIdx.x; i < cnt;
         i += gridDim.x * blockDim.x) {
        float4 p = g_tmp[i];
        unsigned key = g_keys[i];
        int pos = atomicAdd(&g_off[key], 1);
        g_pts[pos] = p;
    }
}

// ---------------- smem layout (float offsets) ----------------
#define OW0A 0        // w0 cols  0-31 : [64][32]
#define OW0B 2052     // w0 cols 32-63 (+16B bank stagger)
#define OW1A 4128     // w1 cols  0-31
#define OW1B 6180     // w1 cols 32-63
#define OW2A 8256     // w2 rows  0-31 : [32][8]
#define OW2B 8516     // w2 rows 32-63
#define OACT 8800     // act exchange: [64][BLK2]
#define SMEM_BYTES ((OACT + 64 * BLK2) * 4)   // 67968

// ---------------- kernel 2: encode + pair-cooperative MLP ---------------
__global__ __launch_bounds__(BLK2, 3)
void k_encode_mlp(const float* __restrict__ table,
                  const float* __restrict__ w0,
                  const float* __restrict__ w1,
                  const float* __restrict__ w2,
                  float* __restrict__ out, int N)
{
    extern __shared__ float sf[];
    int tid = threadIdx.x;

    for (int idx = tid; idx < 4096; idx += BLK2) {
        int i = idx >> 6, j = idx & 63;
        int dst = (j < 32) ? (OW0A + i * 32 + j) : (OW0B + i * 32 + j - 32);
        sf[dst] = w0[idx];
        int dst1 = (j < 32) ? (OW1A + i * 32 + j) : (OW1B + i * 32 + j - 32);
        sf[dst1] = w1[idx];
    }
    for (int idx = tid; idx < 512; idx += BLK2) {
        int i = idx >> 3, j = idx & 7;
        int dst = (i < 32) ? (OW2A + i * 8 + j) : (OW2B + (i - 32) * 8 + j);
        sf[dst] = w2[idx];
    }
    __syncthreads();

    int cnt = g_count;
    int ntiles = (cnt + BLK2 - 1) / BLK2;
    if ((int)blockIdx.x >= ntiles) return;

    int half = tid & 1;
    const float4* myw0 = (const float4*)(sf + (half ? OW0B : OW0A));
    const float4* myw1 = (const float4*)(sf + (half ? OW1B : OW1A));
    const float4* myw2 = (const float4*)(sf + (half ? OW2B : OW2A));
    float* acol = sf + OACT + (tid & ~1);
    int prow = half ? 32 : 0;

    const float4* tbl = (const float4*)table;
    float* dxyz = out + N;
    float* drot = out + (size_t)4 * N;

    for (int tile = blockIdx.x; tile < ntiles; tile += gridDim.x) {
        int slot = tile * BLK2 + tid;
        bool act = slot < cnt;
        float4 p = act ? g_pts[slot] : make_float4(0.f, 0.f, 0.f, 0.f);
        float cx = p.x, cy = p.y, cz = p.z;
        int ipt = __float_as_int(p.w);

        float hP0[32], hP1[32];
        #pragma unroll
        for (int j = 0; j < 32; j++) { hP0[j] = 0.f; hP1[j] = 0.f; }

        // ---- encode (own point) fused with layer-1 (both points) ----
        float sc = 16.f;
        #pragma unroll 1
        for (int l = 0; l < 16; l++) {
            float a0 = 0.f, a1 = 0.f, a2 = 0.f, a3 = 0.f;
            if (act) {
                float px = cx * sc, py = cy * sc, pz = cz * sc;
                float fx = floorf(px), fy = floorf(py), fz = floorf(pz);
                float tx = px - fx, ty = py - fy, tz = pz - fz;
                unsigned ux = (unsigned)fx, uy = (unsigned)fy, uz = (unsigned)fz;
                unsigned hx0 = ux,      hx1 = ux + 1u;
                unsigned hy0 = uy * P1, hy1 = hy0 + P1;
                unsigned hz0 = uz * P2, hz1 = hz0 + P2;
                unsigned base = (unsigned)l * T_SIZE;
                float wxv[2] = {1.f - tx, tx};
                float wyv[2] = {1.f - ty, ty};
                float wzv[2] = {1.f - tz, tz};
                #pragma unroll
                for (int c = 0; c < 8; c++) {
                    unsigned hx = (c & 4) ? hx1 : hx0;
                    unsigned hy = (c & 2) ? hy1 : hy0;
                    unsigned hz = (c & 1) ? hz1 : hz0;
                    unsigned idx = (hx ^ hy ^ hz) & TMASK;
                    float4 f = __ldg(tbl + (base + idx));
                    float w = wxv[(c >> 2) & 1] * wyv[(c >> 1) & 1] * wzv[c & 1];
                    a0 += w * f.x; a1 += w * f.y; a2 += w * f.z; a3 += w * f.w;
                }
            }
            float b0 = __shfl_xor_sync(0xffffffffu, a0, 1);
            float b1 = __shfl_xor_sync(0xffffffffu, a1, 1);
            float b2 = __shfl_xor_sync(0xffffffffu, a2, 1);
            float b3 = __shfl_xor_sync(0xffffffffu, a3, 1);
            float ev[4], qv[4];
            ev[0] = half ? b0 : a0; qv[0] = half ? a0 : b0;
            ev[1] = half ? b1 : a1; qv[1] = half ? a1 : b1;
            ev[2] = half ? b2 : a2; qv[2] = half ? a2 : b2;
            ev[3] = half ? b3 : a3; qv[3] = half ? a3 : b3;

            const float4* wr = myw0 + (l * 4) * 8;
            #pragma unroll
            for (int f = 0; f < 4; f++) {
                float u = ev[f], v = qv[f];
                #pragma unroll
                for (int jj = 0; jj < 8; jj++) {
                    float4 w4 = wr[f * 8 + jj];
                    hP0[4*jj+0] += u * w4.x; hP1[4*jj+0] += v * w4.x;
                    hP0[4*jj+1] += u * w4.y; hP1[4*jj+1] += v * w4.y;
                    hP0[4*jj+2] += u * w4.z; hP1[4*jj+2] += v * w4.z;
                    hP0[4*jj+3] += u * w4.w; hP1[4*jj+3] += v * w4.w;
                }
            }
            sc *= 2.f;
        }

        // relu + spill this lane's half for both points (float2 per row)
        #pragma unroll
        for (int j = 0; j < 32; j++) {
            float2 s;
            s.x = fmaxf(hP0[j], 0.f);
            s.y = fmaxf(hP1[j], 0.f);
            *(float2*)(acol + (prow + j) * BLK2) = s;
        }
        __syncwarp();

        // ---- layer 2: both points, this lane's 32-out half ----
        #pragma unroll
        for (int j = 0; j < 32; j++) { hP0[j] = 0.f; hP1[j] = 0.f; }
        #pragma unroll 4
        for (int i = 0; i < 64; i++) {
            float2 v = *(const float2*)(acol + i * BLK2);
            const float4* wr = myw1 + i * 8;
            #pragma unroll
            for (int jj = 0; jj < 8; jj++) {
                float4 w4 = wr[jj];
                hP0[4*jj+0] += v.x * w4.x; hP1[4*jj+0] += v.y * w4.x;
                hP0[4*jj+1] += v.x * w4.y; hP1[4*jj+1] += v.y * w4.y;
                hP0[4*jj+2] += v.x * w4.z; hP1[4*jj+2] += v.y * w4.z;
                hP0[4*jj+3] += v.x * w4.w; hP1[4*jj+3] += v.y * w4.w;
            }
        }
        __syncwarp();

        // ---- layer 3: partial 8 outs per point from this lane's 32 ins ----
        float o0[8], o1[8];
        #pragma unroll
        for (int k = 0; k < 8; k++) { o0[k] = 0.f; o1[k] = 0.f; }
        #pragma unroll 8
        for (int j = 0; j < 32; j++) {
            float vp = fmaxf(hP0[j], 0.f);
            float vq = fmaxf(hP1[j], 0.f);
            float4 wa = myw2[j * 2];
            float4 wb = myw2[j * 2 + 1];
            o0[0] += vp * wa.x; o0[1] += vp * wa.y;
            o0[2] += vp * wa.z; o0[3] += vp * wa.w;
            o0[4] += vp * wb.x; o0[5] += vp * wb.y;
            o0[6] += vp * wb.z; o0[7] += vp * wb.w;
            o1[0] += vq * wa.x; o1[1] += vq * wa.y;
            o1[2] += vq * wa.z; o1[3] += vq * wa.w;
            o1[4] += vq * wb.x; o1[5] += vq * wb.y;
            o1[6] += vq * wb.z; o1[7] += vq * wb.w;
        }
        #pragma unroll
        for (int k = 0; k < 7; k++) {
            o0[k] += __shfl_xor_sync(0xffffffffu, o0[k], 1);
            o1[k] += __shfl_xor_sync(0xffffffffu, o1[k], 1);
        }

        if (act) {
            float r0 = half ? o1[0] : o0[0];
            float r1 = half ? o1[1] : o0[1];
            float r2 = half ? o1[2] : o0[2];
            float r3 = half ? o1[3] : o0[3];
            float r4 = half ? o1[4] : o0[4];
            float r5 = half ? o1[5] : o0[5];
            float r6 = half ? o1[6] : o0[6];
            dxyz[3 * ipt + 0] = r0;
            dxyz[3 * ipt + 1] = r1;
            dxyz[3 * ipt + 2] = r2;
            drot[4 * ipt + 0] = r3;
            drot[4 * ipt + 1] = r4;
            drot[4 * ipt + 2] = r5;
            drot[4 * ipt + 3] = r6;
        }
    }
}

// ---------------- launch ----------------
extern "C" void kernel_launch(void* const* d_in, const int* in_sizes, int n_in,
                              void* d_out, int out_size)
{
    const float* xyz   = (const float*)d_in[0];
    const float* bmin  = (const float*)d_in[1];
    const float* bmax  = (const float*)d_in[2];
    const float* table = (const float*)d_in[3];
    const float* w0    = (const float*)d_in[4];
    const float* w1    = (const float*)d_in[5];
    const float* w2    = (const float*)d_in[6];
    int N = in_sizes[0] / 3;
    float* out = (float*)d_out;

    void* cptr = nullptr;
    cudaGetSymbolAddress(&cptr, g_count);
    cudaMemsetAsync(cptr, 0, sizeof(int), 0);
    void* hptr = nullptr;
    cudaGetSymbolAddress(&hptr, g_hist);
    cudaMemsetAsync(hptr, 0, NBINS * sizeof(int), 0);

    int grid1 = (N + 255) / 256;
    k_mask_compact<<<grid1, 256>>>(xyz, bmin, bmax, out, N);
    k_scanA<<<64, 128>>>();
    k_scanB<<<1, 512>>>();
    k_scatter<<<512, 256>>>();

    cudaFuncSetAttribute(k_encode_mlp,
                         cudaFuncAttributeMaxDynamicSharedMemorySize, SMEM_BYTES);
    k_encode_mlp<<<444, BLK2, SMEM_BYTES>>>(table, w0, w1, w2, out, N);
}

// round 7
// speedup vs baseline: 1.6735x; 1.6735x over previous
#include <cuda_runtime.h>
#include <cuda_fp16.h>
#include <cstdint>

// ---------------- problem constants ----------------
#define L_LEVELS 16
#define T_SIZE 32768
#define TMASK  32767u
#define P1 2654435761u
#define P2 805459861u
#define MAXN (1 << 20)
#define NBINS 32768
#define BLOCK2 128

// scratch (no cudaMalloc allowed)
__device__ float4 g_tmp[MAXN];    // compacted, unsorted
__device__ float4 g_pts[MAXN];    // morton-sorted
__device__ unsigned g_keys[MAXN];
__device__ int g_hist[NBINS];
__device__ int g_off[NBINS];
__device__ int g_blocksum[64];
__device__ int g_count;
__device__ __half g_tblh[L_LEVELS * T_SIZE * 4];   // 4 MB fp16 table

__device__ __forceinline__ unsigned part5(unsigned x) {
    return ((x & 16u) << 8) | ((x & 8u) << 6) | ((x & 4u) << 4) |
           ((x & 2u) << 2) | (x & 1u);
}

// ---------------- kernel 0: convert table f32 -> fp16 -------------------
__global__ void k_convert(const float* __restrict__ t)
{
    int i = blockIdx.x * blockDim.x + threadIdx.x;   // over half2 pairs
    int total = L_LEVELS * T_SIZE * 4 / 2;
    if (i < total) {
        float2 v = ((const float2*)t)[i];
        ((__half2*)g_tblh)[i] = __floats2half2_rn(v.x, v.y);
    }
}

// ---------------- kernel 1: mask + defaults + compact + histogram ------
__global__ void k_mask_compact(const float* __restrict__ xyz,
                               const float* __restrict__ bmin,
                               const float* __restrict__ bmax,
                               float* __restrict__ out, int N)
{
    int i = blockIdx.x * blockDim.x + threadIdx.x;
    bool inb = false;
    float cx = 0.f, cy = 0.f, cz = 0.f;

    if (i < N) {
        float bx0 = bmin[0], by0 = bmin[1], bz0 = bmin[2];
        float bx1 = bmax[0], by1 = bmax[1], bz1 = bmax[2];
        float x = xyz[3 * i + 0];
        float y = xyz[3 * i + 1];
        float z = xyz[3 * i + 2];
        cx = (x - bx0) / (bx1 - bx0);
        cy = (y - by0) / (by1 - by0);
        cz = (z - bz0) / (bz1 - bz0);
        inb = (cx >= 0.f) & (cx <= 1.f) &
              (cy >= 0.f) & (cy <= 1.f) &
              (cz >= 0.f) & (cz <= 1.f);

        out[i] = inb ? 1.f : 0.f;
        float* dxyz = out + N;
        float* drot = out + (size_t)4 * N;
        dxyz[3 * i + 0] = 0.f;
        dxyz[3 * i + 1] = 0.f;
        dxyz[3 * i + 2] = 0.f;
        drot[4 * i + 0] = 1.f;
        drot[4 * i + 1] = 0.f;
        drot[4 * i + 2] = 0.f;
        drot[4 * i + 3] = 0.f;
    }

    unsigned m = __ballot_sync(0xffffffffu, inb);
    if (inb) {
        int lane = threadIdx.x & 31;
        int leader = __ffs(m) - 1;
        int base = 0;
        if (lane == leader) base = atomicAdd(&g_count, __popc(m));
        base = __shfl_sync(m, base, leader);
        int slot = base + __popc(m & ((1u << lane) - 1u));
        cx = fminf(fmaxf(cx, 0.f), 1.f);
        cy = fminf(fmaxf(cy, 0.f), 1.f);
        cz = fminf(fmaxf(cz, 0.f), 1.f);
        g_tmp[slot] = make_float4(cx, cy, cz, __int_as_float(i));
        unsigned qx = min(31u, (unsigned)(cx * 32.f));
        unsigned qy = min(31u, (unsigned)(cy * 32.f));
        unsigned qz = min(31u, (unsigned)(cz * 32.f));
        unsigned key = part5(qx) | (part5(qy) << 1) | (part5(qz) << 2);
        g_keys[slot] = key;
        atomicAdd(&g_hist[key], 1);
    }
}

// ---------------- scan phase A: 64 blocks, local scan of 512 bins -------
__global__ void k_scanA()
{
    __shared__ int wsum[16];
    int b = blockIdx.x;
    int tid = threadIdx.x;            // 128 threads, 4 bins each
    int base = b * 512 + tid * 4;
    int4 c = *(const int4*)&g_hist[base];
    int s = c.x + c.y + c.z + c.w;

    int lane = tid & 31, wid = tid >> 5;
    int v = s;
    #pragma unroll
    for (int d = 1; d < 32; d <<= 1) {
        int t = __shfl_up_sync(0xffffffffu, v, d);
        if (lane >= d) v += t;
    }
    if (lane == 31) wsum[wid] = v;
    __syncthreads();
    if (tid == 0) {
        int acc = 0;
        #pragma unroll
        for (int w = 0; w < 4; w++) { int t = wsum[w]; wsum[w] = acc; acc += t; }
        g_blocksum[b] = acc;
    }
    __syncthreads();
    int excl = v - s + wsum[wid];
    int4 o;
    o.x = excl; o.y = excl + c.x; o.z = o.y + c.y; o.w = o.z + c.z;
    *(int4*)&g_off[base] = o;
}

// ---------------- scan phase B: add block prefixes (1 block) ------------
__global__ void k_scanB()
{
    __shared__ int pre[64];
    int tid = threadIdx.x;            // 512 threads
    if (tid == 0) {
        int acc = 0;
        #pragma unroll
        for (int b = 0; b < 64; b++) { int t = g_blocksum[b]; pre[b] = acc; acc += t; }
    }
    __syncthreads();
    for (int idx = tid; idx < NBINS / 4; idx += 512) {
        int b = idx / 128;
        int add = pre[b];
        int4 v = *(int4*)&g_off[idx * 4];
        v.x += add; v.y += add; v.z += add; v.w += add;
        *(int4*)&g_off[idx * 4] = v;
    }
}

// ---------------- scatter into sorted order -----------------------------
__global__ void k_scatter()
{
    int cnt = g_count;
    for (int i = blockIdx.x * blockDim.x + threadIdx.x; i < cnt;
         i += gridDim.x * blockDim.x) {
        float4 p = g_tmp[i];
        unsigned key = g_keys[i];
        int pos = atomicAdd(&g_off[key], 1);
        g_pts[pos] = p;
    }
}

// ---------------- kernel 2: hash encode (fp16 table) + MLP --------------
// smem: [w0 4096][w1 4096][w2 512][act 64*BLOCK2]
__global__ __launch_bounds__(BLOCK2, 3)
void k_encode_mlp(const float* __restrict__ w0,
                  const float* __restrict__ w1,
                  const float* __restrict__ w2,
                  float* __restrict__ out, int N)
{
    extern __shared__ float sm[];
    float* sw0  = sm;            // 4096 floats
    float* sw1  = sm + 4096;     // 4096 floats
    float* sw2  = sm + 8192;     // 512 floats
    float* sact = sm + 8704;     // 64 * BLOCK2 floats

    int tid = threadIdx.x;
    int cnt = g_count;
    if ((int)(blockIdx.x * BLOCK2) >= cnt) return;

    for (int k = tid; k < 4096 / 4; k += BLOCK2)
        ((float4*)sw0)[k] = ((const float4*)w0)[k];
    for (int k = tid; k < 4096 / 4; k += BLOCK2)
        ((float4*)sw1)[k] = ((const float4*)w1)[k];
    for (int k = tid; k < 512 / 4; k += BLOCK2)
        ((float4*)sw2)[k] = ((const float4*)w2)[k];
    __syncthreads();

    const uint2* tbl = (const uint2*)g_tblh;   // 8B = 4 fp16 features
    float* dxyz = out + N;
    float* drot = out + (size_t)4 * N;

    for (int slot = blockIdx.x * BLOCK2 + tid; slot < cnt;
         slot += gridDim.x * BLOCK2) {
        float4 p = g_pts[slot];
        float cx = p.x, cy = p.y, cz = p.z;
        int ipt = __float_as_int(p.w);

        float h[64];
        #pragma unroll
        for (int j = 0; j < 64; j++) h[j] = 0.f;

        float sc = 16.f;
        #pragma unroll 1
        for (int l = 0; l < L_LEVELS; l++) {
            float px = cx * sc, py = cy * sc, pz = cz * sc;
            float fx = floorf(px), fy = floorf(py), fz = floorf(pz);
            float tx = px - fx, ty = py - fy, tz = pz - fz;
            unsigned ux = (unsigned)fx, uy = (unsigned)fy, uz = (unsigned)fz;

            unsigned hx0 = ux,        hx1 = ux + 1u;
            unsigned hy0 = uy * P1,   hy1 = hy0 + P1;
            unsigned hz0 = uz * P2,   hz1 = hz0 + P2;
            unsigned base = (unsigned)l * T_SIZE;

            float wx[2] = {1.f - tx, tx};
            float wy[2] = {1.f - ty, ty};
            float wz[2] = {1.f - tz, tz};

            float a0 = 0.f, a1 = 0.f, a2 = 0.f, a3 = 0.f;
            #pragma unroll
            for (int c = 0; c < 8; c++) {
                unsigned hx = (c & 4) ? hx1 : hx0;
                unsigned hy = (c & 2) ? hy1 : hy0;
                unsigned hz = (c & 1) ? hz1 : hz0;
                unsigned idx = (hx ^ hy ^ hz) & TMASK;
                uint2 raw = __ldg(tbl + (base + idx));
                __half2 p01 = *reinterpret_cast<__half2*>(&raw.x);
                __half2 p23 = *reinterpret_cast<__half2*>(&raw.y);
                float2 f01 = __half22float2(p01);
                float2 f23 = __half22float2(p23);
                float w = wx[(c >> 2) & 1] * wy[(c >> 1) & 1] * wz[c & 1];
                a0 += w * f01.x; a1 += w * f01.y;
                a2 += w * f23.x; a3 += w * f23.y;
            }

            float av[4] = {a0, a1, a2, a3};
            #pragma unroll
            for (int f = 0; f < 4; f++) {
                const float4* wr = (const float4*)(sw0 + ((l * 4 + f) << 6));
                float a = av[f];
                #pragma unroll
                for (int jj = 0; jj < 16; jj++) {
                    float4 wv = wr[jj];
                    h[4 * jj + 0] += a * wv.x;
                    h[4 * jj + 1] += a * wv.y;
                    h[4 * jj + 2] += a * wv.z;
                    h[4 * jj + 3] += a * wv.w;
                }
            }
            sc *= 2.f;
        }

        #pragma unroll
        for (int j = 0; j < 64; j++)
            sact[j * BLOCK2 + tid] = fmaxf(h[j], 0.f);

        #pragma unroll
        for (int j = 0; j < 64; j++) h[j] = 0.f;
        #pragma unroll 4
        for (int i = 0; i < 64; i++) {
            float v = sact[i * BLOCK2 + tid];
            const float4* wr = (const float4*)(sw1 + (i << 6));
            #pragma unroll
            for (int jj = 0; jj < 16; jj++) {
                float4 wv = wr[jj];
                h[4 * jj + 0] += v * wv.x;
                h[4 * jj + 1] += v * wv.y;
                h[4 * jj + 2] += v * wv.z;
                h[4 * jj + 3] += v * wv.w;
            }
        }
        #pragma unroll
        for (int j = 0; j < 64; j++)
            sact[j * BLOCK2 + tid] = fmaxf(h[j], 0.f);

        float o[8];
        #pragma unroll
        for (int k = 0; k < 8; k++) o[k] = 0.f;
        #pragma unroll 8
        for (int i = 0; i < 64; i++) {
            float v = sact[i * BLOCK2 + tid];
            const float4* wr = (const float4*)(sw2 + (i << 3));
            float4 wa = wr[0], wb = wr[1];
            o[0] += v * wa.x; o[1] += v * wa.y; o[2] += v * wa.z; o[3] += v * wa.w;
            o[4] += v * wb.x; o[5] += v * wb.y; o[6] += v * wb.z; o[7] += v * wb.w;
        }

        dxyz[3 * ipt + 0] = o[0];
        dxyz[3 * ipt + 1] = o[1];
        dxyz[3 * ipt + 2] = o[2];
        drot[4 * ipt + 0] = o[3];
        drot[4 * ipt + 1] = o[4];
        drot[4 * ipt + 2] = o[5];
        drot[4 * ipt + 3] = o[6];
    }
}

// ---------------- launch ----------------
extern "C" void kernel_launch(void* const* d_in, const int* in_sizes, int n_in,
                              void* d_out, int out_size)
{
    const float* xyz   = (const float*)d_in[0];
    const float* bmin  = (const float*)d_in[1];
    const float* bmax  = (const float*)d_in[2];
    const float* table = (const float*)d_in[3];
    const float* w0    = (const float*)d_in[4];
    const float* w1    = (const float*)d_in[5];
    const float* w2    = (const float*)d_in[6];
    int N = in_sizes[0] / 3;
    float* out = (float*)d_out;

    void* cptr = nullptr;
    cudaGetSymbolAddress(&cptr, g_count);
    cudaMemsetAsync(cptr, 0, sizeof(int), 0);
    void* hptr = nullptr;
    cudaGetSymbolAddress(&hptr, g_hist);
    cudaMemsetAsync(hptr, 0, NBINS * sizeof(int), 0);

    int nconv = L_LEVELS * T_SIZE * 4 / 2;
    k_convert<<<(nconv + 255) / 256, 256>>>(table);

    int grid1 = (N + 255) / 256;
    k_mask_compact<<<grid1, 256>>>(xyz, bmin, bmax, out, N);
    k_scanA<<<64, 128>>>();
    k_scanB<<<1, 512>>>();
    k_scatter<<<512, 256>>>();

    int smem = (8704 + 64 * BLOCK2) * (int)sizeof(float);  // 67584 B
    cudaFuncSetAttribute(k_encode_mlp,
                         cudaFuncAttributeMaxDynamicSharedMemorySize, smem);
    k_encode_mlp<<<444, BLOCK2, smem>>>(w0, w1, w2, out, N);
}